// round 6
// baseline (speedup 1.0000x reference)
#include <cuda_runtime.h>
#include <cuda_bf16.h>
#include <cooperative_groups.h>
#include <stdint.h>

namespace cg = cooperative_groups;

// Problem dims
#define NB 32
#define NS 1024
#define NC 12
#define NE 256
#define NH 512
#define NT 50
#define NTOK (NB*NS)          // 32768

// ---------------- device scratch (allocation-free) ----------------
__device__ float g_WcihT[NE * 4 * NE];            // [k=256][1024] col 4u+g <- row g*256+u
__device__ float g_WchhT[NE * 4 * NE];
__device__ float g_bcp[4 * NE];
__device__ float g_WwihT[2 * NE * 4 * NH];        // [k=512][2048]
__device__ float g_WwhhT[NH * 4 * NH];            // [k=512][2048]
__device__ float g_bwp[4 * NH];

__device__ float g_HcA[NTOK * NE];                // char h ping
__device__ float g_HcB[NTOK * NE];                // char h pong (holds final char_feat)
__device__ float g_Cc [NTOK * NE];                // char c state
__device__ float g_XW [(size_t)NTOK * 4 * NH];    // word-input preacts + bias, [n][2048]
__device__ float g_Hsave[(size_t)NTOK * NH];      // word hidden trace [n][512]
__device__ float g_Cw [NB * NH];                  // word c state (fallback path only)

// ---------------- math helpers ----------------
__device__ __forceinline__ float sigm_(float x) {
    return __fdividef(1.f, 1.f + __expf(-x));
}
__device__ __forceinline__ float tanh_(float x) {
    return __fdividef(2.f, 1.f + __expf(-2.f * x)) - 1.f;
}

// ---------------- prep: permute/transpose weights ----------------
__global__ void prep_all_kernel(const float* __restrict__ Wc_ih,
                                const float* __restrict__ Wc_hh,
                                const float* __restrict__ bc,
                                const float* __restrict__ Ww_ih,
                                const float* __restrict__ Ww_hh,
                                const float* __restrict__ bw)
{
    const int stride = gridDim.x * blockDim.x;
    for (int idx = blockIdx.x * blockDim.x + threadIdx.x; idx < 1048576; idx += stride) {
        // word weights: [k=512][c=2048], WT[k*2048 + (4u+g)] = W[(g*512+u)*Kdim + k]
        {
            int c = idx & 2047, k = idx >> 11;      // k in [0,512)
            int u = c >> 2, g = c & 3;
            g_WwihT[idx] = Ww_ih[(g * NH + u) * (2 * NE) + k];
            g_WwhhT[idx] = Ww_hh[(g * NH + u) * NH + k];
        }
        // char weights: [k=256][c=1024]
        if (idx < 262144) {
            int c = idx & 1023, k = idx >> 10;      // k in [0,256)
            int u = c >> 2, g = c & 3;
            g_WcihT[idx] = Wc_ih[(g * NE + u) * NE + k];
            g_WchhT[idx] = Wc_hh[(g * NE + u) * NE + k];
        }
        if (idx < 2048) {
            int u = idx >> 2, g = idx & 3;
            g_bwp[idx] = bw[g * NH + u];
        }
        if (idx < 1024) {
            int u = idx >> 2, g = idx & 3;
            g_bcp[idx] = bc[g * NE + u];
        }
    }
}

// ---------------- char LSTM step ----------------
// CTA: 64 tokens x 256 gate-cols (64 units). 256 threads: tx=unit(64), ty=tokgrp(4).
// Thread micro-tile: 16 tokens x 4 gate cols (= 1 unit, all gates) -> fused pointwise.
__global__ __launch_bounds__(256, 2)
void char_step_kernel(const int* __restrict__ char_idx,
                      const float* __restrict__ char_emb, int t)
{
    __shared__ float Xs[16][68];     // [k][token], padded
    __shared__ float Ws[16][260];    // [k][col],   padded
    __shared__ int   idxs[64];

    const int tid = threadIdx.x;
    const int tx = tid & 63;
    const int ty = tid >> 6;
    const int tok0 = blockIdx.x * 64;
    const int c0 = blockIdx.y * 256;

    float* hnew        = (t & 1) ? g_HcB : g_HcA;
    const float* hprev = (t & 1) ? g_HcA : g_HcB;

    float acc[16][4];
#pragma unroll
    for (int r = 0; r < 16; r++) {
        acc[r][0] = 0.f; acc[r][1] = 0.f; acc[r][2] = 0.f; acc[r][3] = 0.f;
    }

    if (tid < 64) idxs[tid] = char_idx[(tok0 + tid) * NC + t];
    __syncthreads();

    const int npass = (t == 0) ? 1 : 2;
    for (int pass = 0; pass < npass; pass++) {
        const float* W = pass ? g_WchhT : g_WcihT;
        for (int kc = 0; kc < 16; kc++) {
            const int k0 = kc * 16;
            // load Xs[k][tok] (transposed): thread loads float4 along k for one token
            {
                int tok = tid >> 2, kq = tid & 3;
                float4 v;
                if (pass == 0)
                    v = *(const float4*)&char_emb[idxs[tok] * NE + k0 + kq * 4];
                else
                    v = *(const float4*)&hprev[(tok0 + tok) * NE + k0 + kq * 4];
                Xs[kq * 4 + 0][tok] = v.x;
                Xs[kq * 4 + 1][tok] = v.y;
                Xs[kq * 4 + 2][tok] = v.z;
                Xs[kq * 4 + 3][tok] = v.w;
            }
            // load Ws[k][c]: 16x256 = 1024 float4, 4 per thread
#pragma unroll
            for (int j = 0; j < 4; j++) {
                int f = tid + j * 256;
                int kk = f >> 6, cq = f & 63;
                *(float4*)&Ws[kk][cq * 4] =
                    *(const float4*)&W[(k0 + kk) * 1024 + c0 + cq * 4];
            }
            __syncthreads();
#pragma unroll
            for (int k = 0; k < 16; k++) {
                float4 b = *(float4*)&Ws[k][tx * 4];
                float a[16];
#pragma unroll
                for (int q = 0; q < 4; q++) {
                    float4 av = *(float4*)&Xs[k][ty * 16 + q * 4];
                    a[q * 4 + 0] = av.x; a[q * 4 + 1] = av.y;
                    a[q * 4 + 2] = av.z; a[q * 4 + 3] = av.w;
                }
#pragma unroll
                for (int r = 0; r < 16; r++) {
                    acc[r][0] += a[r] * b.x;
                    acc[r][1] += a[r] * b.y;
                    acc[r][2] += a[r] * b.z;
                    acc[r][3] += a[r] * b.w;
                }
            }
            __syncthreads();
        }
    }

    // fused LSTM pointwise epilogue
    const int u = (c0 >> 2) + tx;                  // global unit 0..255
    float4 bias = *(const float4*)&g_bcp[c0 + tx * 4];
#pragma unroll
    for (int r = 0; r < 16; r++) {
        int tok = tok0 + ty * 16 + r;
        float gi = acc[r][0] + bias.x;
        float gf = acc[r][1] + bias.y;
        float gg = acc[r][2] + bias.z;
        float go = acc[r][3] + bias.w;
        float cp = (t == 0) ? 0.f : g_Cc[tok * NE + u];
        float cn = sigm_(gf) * cp + sigm_(gi) * tanh_(gg);
        float h  = sigm_(go) * tanh_(cn);
        g_Cc[tok * NE + u] = cn;
        hnew[tok * NE + u] = h;
    }
}

// ---------------- word-input GEMM: XW = [we ; char_feat] @ WwihT + bw ----------------
__global__ __launch_bounds__(256, 2)
void xw_kernel(const int* __restrict__ word_idx, const float* __restrict__ word_emb)
{
    __shared__ float Xs[16][68];
    __shared__ float Ws[16][260];
    __shared__ int   idxs[64];

    const int tid = threadIdx.x;
    const int tx = tid & 63;
    const int ty = tid >> 6;
    const int tok0 = blockIdx.x * 64;
    const int c0 = blockIdx.y * 256;

    float acc[16][4];
#pragma unroll
    for (int r = 0; r < 16; r++) {
        acc[r][0] = 0.f; acc[r][1] = 0.f; acc[r][2] = 0.f; acc[r][3] = 0.f;
    }

    if (tid < 64) idxs[tid] = word_idx[tok0 + tid];
    __syncthreads();

    for (int kc = 0; kc < 32; kc++) {
        const int k0 = kc * 16;
        {
            int tok = tid >> 2, kq = tid & 3;
            float4 v;
            if (kc < 16)
                v = *(const float4*)&word_emb[(size_t)idxs[tok] * NE + k0 + kq * 4];
            else
                v = *(const float4*)&g_HcB[(tok0 + tok) * NE + (k0 - NE) + kq * 4];
            Xs[kq * 4 + 0][tok] = v.x;
            Xs[kq * 4 + 1][tok] = v.y;
            Xs[kq * 4 + 2][tok] = v.z;
            Xs[kq * 4 + 3][tok] = v.w;
        }
#pragma unroll
        for (int j = 0; j < 4; j++) {
            int f = tid + j * 256;
            int kk = f >> 6, cq = f & 63;
            *(float4*)&Ws[kk][cq * 4] =
                *(const float4*)&g_WwihT[(k0 + kk) * 2048 + c0 + cq * 4];
        }
        __syncthreads();
#pragma unroll
        for (int k = 0; k < 16; k++) {
            float4 b = *(float4*)&Ws[k][tx * 4];
            float a[16];
#pragma unroll
            for (int q = 0; q < 4; q++) {
                float4 av = *(float4*)&Xs[k][ty * 16 + q * 4];
                a[q * 4 + 0] = av.x; a[q * 4 + 1] = av.y;
                a[q * 4 + 2] = av.z; a[q * 4 + 3] = av.w;
            }
#pragma unroll
            for (int r = 0; r < 16; r++) {
                acc[r][0] += a[r] * b.x;
                acc[r][1] += a[r] * b.y;
                acc[r][2] += a[r] * b.z;
                acc[r][3] += a[r] * b.w;
            }
        }
        __syncthreads();
    }

    float4 bias = *(const float4*)&g_bwp[c0 + tx * 4];
#pragma unroll
    for (int r = 0; r < 16; r++) {
        int tok = tok0 + ty * 16 + r;
        float4 o;
        o.x = acc[r][0] + bias.x;
        o.y = acc[r][1] + bias.y;
        o.z = acc[r][2] + bias.z;
        o.w = acc[r][3] + bias.w;
        *(float4*)&g_XW[(size_t)tok * 2048 + c0 + tx * 4] = o;
    }
}

// ---------------- word LSTM, cooperative (1 launch, grid.sync) ----------------
// 128 CTAs; CTA owns 16 gate-cols (4 units) x all 32 batches. c-state in register.
// Launched via cudaLaunchCooperativeKernel ONLY (validated residency; cannot hang).
__global__ __launch_bounds__(128, 1)
void word_coop_kernel(int /*dummy*/)
{
    cg::grid_group grid = cg::this_grid();

    extern __shared__ float sm[];
    float* ws = sm;              // [512][20] weight slice (16 cols, padded to 20)
    float* hs = sm + 512 * 20;   // [512][33] h_prev transposed [k][b]

    const int tid = threadIdx.x;
    const int b  = tid >> 2;
    const int ul = tid & 3;
    const int c0 = blockIdx.x * 16;
    const int ug = (c0 >> 2) + ul;                 // global unit 0..511

    // load weight slice once for all 1024 steps
    for (int idx = tid; idx < 512 * 16; idx += 128) {
        int k = idx >> 4, j = idx & 15;
        ws[k * 20 + j] = g_WwhhT[k * 2048 + c0 + j];
    }

    float c = 0.f;
    for (int t = 0; t < NS; t++) {
        if (t == 0) {
            for (int idx = tid; idx < 512 * 33; idx += 128) hs[idx] = 0.f;
        } else {
#pragma unroll 4
            for (int idx = tid; idx < 16384; idx += 128) {
                int bb = idx >> 9, k = idx & 511;
                hs[k * 33 + bb] = g_Hsave[(size_t)((bb << 10) + (t - 1)) * NH + k];
            }
        }
        __syncthreads();

        float4 a = *(const float4*)&g_XW[(size_t)((b << 10) + t) * 2048 + c0 + ul * 4];
        float4 acc = make_float4(0.f, 0.f, 0.f, 0.f);
#pragma unroll 8
        for (int k = 0; k < 512; k++) {
            float hb = hs[k * 33 + b];
            float4 w = *(float4*)&ws[k * 20 + ul * 4];
            acc.x += hb * w.x;
            acc.y += hb * w.y;
            acc.z += hb * w.z;
            acc.w += hb * w.w;
        }
        float gi = acc.x + a.x;     // bias already folded into XW
        float gf = acc.y + a.y;
        float gg = acc.z + a.z;
        float go = acc.w + a.w;
        c = sigm_(gf) * c + sigm_(gi) * tanh_(gg);
        float h = sigm_(go) * tanh_(c);
        g_Hsave[(size_t)((b << 10) + t) * NH + ug] = h;

        grid.sync();   // grid-wide barrier with memory ordering; also fences hs reuse
    }
}

// ---------------- word LSTM fallback: one launch per step ----------------
__global__ __launch_bounds__(128, 1)
void word_step_kernel(int t)
{
    extern __shared__ float sm[];
    float* ws = sm;
    float* hs = sm + 512 * 20;

    const int tid = threadIdx.x;
    const int b  = tid >> 2;
    const int ul = tid & 3;
    const int c0 = blockIdx.x * 16;
    const int ug = (c0 >> 2) + ul;

    for (int idx = tid; idx < 512 * 16; idx += 128) {
        int k = idx >> 4, j = idx & 15;
        ws[k * 20 + j] = g_WwhhT[k * 2048 + c0 + j];
    }
    if (t == 0) {
        for (int idx = tid; idx < 512 * 33; idx += 128) hs[idx] = 0.f;
    } else {
#pragma unroll 4
        for (int idx = tid; idx < 16384; idx += 128) {
            int bb = idx >> 9, k = idx & 511;
            hs[k * 33 + bb] = g_Hsave[(size_t)((bb << 10) + (t - 1)) * NH + k];
        }
    }
    __syncthreads();

    float4 a = *(const float4*)&g_XW[(size_t)((b << 10) + t) * 2048 + c0 + ul * 4];
    float4 acc = make_float4(0.f, 0.f, 0.f, 0.f);
#pragma unroll 8
    for (int k = 0; k < 512; k++) {
        float hb = hs[k * 33 + b];
        float4 w = *(float4*)&ws[k * 20 + ul * 4];
        acc.x += hb * w.x;
        acc.y += hb * w.y;
        acc.z += hb * w.z;
        acc.w += hb * w.w;
    }
    float gi = acc.x + a.x;
    float gf = acc.y + a.y;
    float gg = acc.z + a.z;
    float go = acc.w + a.w;
    float c = (t == 0) ? 0.f : g_Cw[b * NH + ug];
    c = sigm_(gf) * c + sigm_(gi) * tanh_(gg);
    float h = sigm_(go) * tanh_(c);
    g_Cw[b * NH + ug] = c;
    g_Hsave[(size_t)((b << 10) + t) * NH + ug] = h;
}

// ---------------- logits + log_softmax ----------------
// Block: 256 thr = 4 tokens x 64 tags. Wt transposed in smem [k][64].
__global__ __launch_bounds__(256, 1)
void logits_kernel(const float* __restrict__ Wt, const float* __restrict__ bt,
                   float* __restrict__ out)
{
    extern __shared__ float sm[];
    float* Wts = sm;               // [512][65]
    float* hs  = sm + 512 * 65;    // [4][512]
    __shared__ float sl[4][64];

    const int tid = threadIdx.x;
    for (int idx = tid; idx < 512 * 64; idx += 256) {
        int tg = idx >> 9, k = idx & 511;
        Wts[k * 65 + tg] = (tg < NT) ? Wt[tg * NH + k] : 0.f;
    }
    const int tokl = tid >> 6, tag = tid & 63;
    const int wid = tid >> 5, lane = tid & 31;
    float btv = (tag < NT) ? bt[tag] : 0.f;

    for (int tb = blockIdx.x; tb < NTOK / 4; tb += gridDim.x) {
        __syncthreads();
        for (int idx = tid; idx < 2048; idx += 256) {
            int tk = idx >> 9, k = idx & 511;
            hs[tk * 512 + k] = g_Hsave[(size_t)(tb * 4 + tk) * NH + k];
        }
        __syncthreads();
        float acc = 0.f;
#pragma unroll 8
        for (int k = 0; k < 512; k++)
            acc += hs[tokl * 512 + k] * Wts[k * 65 + tag];
        sl[tokl][tag] = (tag < NT) ? (acc + btv) : -1e30f;
        __syncthreads();
        if (wid < 4) {
            float l0 = sl[wid][lane], l1 = sl[wid][lane + 32];
            float m = fmaxf(l0, l1);
#pragma unroll
            for (int o = 16; o; o >>= 1) m = fmaxf(m, __shfl_xor_sync(0xffffffffu, m, o));
            float s = __expf(l0 - m) + __expf(l1 - m);
#pragma unroll
            for (int o = 16; o; o >>= 1) s += __shfl_xor_sync(0xffffffffu, s, o);
            float lse = m + __logf(s);
            int n = tb * 4 + wid;
            for (int j = lane; j < NT; j += 32)
                out[(size_t)n * NT + j] = sl[wid][j] - lse;
        }
    }
}

// ---------------- launch ----------------
extern "C" void kernel_launch(void* const* d_in, const int* in_sizes, int n_in,
                              void* d_out, int out_size)
{
    const int*   char_idx = (const int*)d_in[0];
    const int*   word_idx = (const int*)d_in[1];
    const float* char_emb = (const float*)d_in[2];
    const float* word_emb = (const float*)d_in[3];
    const float* Wc_ih    = (const float*)d_in[4];
    const float* Wc_hh    = (const float*)d_in[5];
    const float* bc       = (const float*)d_in[6];
    const float* Ww_ih    = (const float*)d_in[7];
    const float* Ww_hh    = (const float*)d_in[8];
    const float* bw       = (const float*)d_in[9];
    const float* Wt       = (const float*)d_in[10];
    const float* bt       = (const float*)d_in[11];
    float* out = (float*)d_out;

    const int word_smem   = (512 * 20 + 512 * 33) * 4;   // 108544 B
    const int logits_smem = (512 * 65 + 4 * 512) * 4;    // 141312 B
    cudaFuncSetAttribute(word_coop_kernel,
                         cudaFuncAttributeMaxDynamicSharedMemorySize, word_smem);
    cudaFuncSetAttribute(word_step_kernel,
                         cudaFuncAttributeMaxDynamicSharedMemorySize, word_smem);
    cudaFuncSetAttribute(logits_kernel,
                         cudaFuncAttributeMaxDynamicSharedMemorySize, logits_smem);

    // Deterministic host-side decision: cooperative path only if the device
    // guarantees 128 co-resident CTAs (pure queries, capture-legal).
    int dev = 0;
    cudaGetDevice(&dev);
    int numSM = 0, coopAttr = 0, perSM = 0;
    cudaDeviceGetAttribute(&numSM, cudaDevAttrMultiProcessorCount, dev);
    cudaDeviceGetAttribute(&coopAttr, cudaDevAttrCooperativeLaunch, dev);
    cudaOccupancyMaxActiveBlocksPerMultiprocessor(&perSM, word_coop_kernel, 128, word_smem);
    const bool coop_ok = (coopAttr != 0) && (perSM >= 1) && (numSM >= 128);

    prep_all_kernel<<<4096, 256>>>(Wc_ih, Wc_hh, bc, Ww_ih, Ww_hh, bw);

    for (int t = 0; t < NC; t++)
        char_step_kernel<<<dim3(NTOK / 64, 4), 256>>>(char_idx, char_emb, t);

    xw_kernel<<<dim3(NTOK / 64, 8), 256>>>(word_idx, word_emb);

    if (coop_ok) {
        int dummy = 0;
        void* kargs[] = { &dummy };
        cudaLaunchCooperativeKernel((void*)word_coop_kernel,
                                    dim3(128), dim3(128),
                                    kargs, (size_t)word_smem, (cudaStream_t)0);
    } else {
        for (int t = 0; t < NS; t++)
            word_step_kernel<<<128, 128, word_smem>>>(t);
    }

    logits_kernel<<<148, 256, logits_smem>>>(Wt, bt, out);
}

// round 7
// speedup vs baseline: 1.3655x; 1.3655x over previous
#include <cuda_runtime.h>
#include <cuda_bf16.h>
#include <cooperative_groups.h>
#include <stdint.h>

namespace cg = cooperative_groups;

// Problem dims
#define NB 32
#define NS 1024
#define NC 12
#define NE 256
#define NH 512
#define NT 50
#define NTOK (NB*NS)          // 32768

// ---------------- device scratch (allocation-free) ----------------
__device__ float g_WcihT[NE * 4 * NE];            // [k=256][1024] col 4u+g <- row g*256+u
__device__ float g_WchhT[NE * 4 * NE];
__device__ float g_bcp[4 * NE];
__device__ float g_WwihT[2 * NE * 4 * NH];        // [k=512][2048]
__device__ float g_WwhhT[NH * 4 * NH];            // [k=512][2048]
__device__ float g_bwp[4 * NH];

__device__ float g_HcA[NTOK * NE];                // char h ping
__device__ float g_HcB[NTOK * NE];                // char h pong (holds final char_feat)
__device__ float g_Cc [NTOK * NE];                // char c state
__device__ float g_XW [(size_t)NTOK * 4 * NH];    // word-input preacts + bias, [n][2048]
__device__ float g_Hsave[(size_t)NTOK * NH];      // word hidden trace [n][512]
__device__ float g_Cw [NB * NH];                  // word c state (fallback path only)

// ---------------- math helpers ----------------
__device__ __forceinline__ float sigm_(float x) {
    return __fdividef(1.f, 1.f + __expf(-x));
}
__device__ __forceinline__ float tanh_(float x) {
    return __fdividef(2.f, 1.f + __expf(-2.f * x)) - 1.f;
}

// ---------------- prep: permute/transpose weights ----------------
__global__ void prep_all_kernel(const float* __restrict__ Wc_ih,
                                const float* __restrict__ Wc_hh,
                                const float* __restrict__ bc,
                                const float* __restrict__ Ww_ih,
                                const float* __restrict__ Ww_hh,
                                const float* __restrict__ bw)
{
    const int stride = gridDim.x * blockDim.x;
    for (int idx = blockIdx.x * blockDim.x + threadIdx.x; idx < 1048576; idx += stride) {
        // word weights: [k=512][c=2048], WT[k*2048 + (4u+g)] = W[(g*512+u)*Kdim + k]
        {
            int c = idx & 2047, k = idx >> 11;      // k in [0,512)
            int u = c >> 2, g = c & 3;
            g_WwihT[idx] = Ww_ih[(g * NH + u) * (2 * NE) + k];
            g_WwhhT[idx] = Ww_hh[(g * NH + u) * NH + k];
        }
        // char weights: [k=256][c=1024]
        if (idx < 262144) {
            int c = idx & 1023, k = idx >> 10;      // k in [0,256)
            int u = c >> 2, g = c & 3;
            g_WcihT[idx] = Wc_ih[(g * NE + u) * NE + k];
            g_WchhT[idx] = Wc_hh[(g * NE + u) * NE + k];
        }
        if (idx < 2048) {
            int u = idx >> 2, g = idx & 3;
            g_bwp[idx] = bw[g * NH + u];
        }
        if (idx < 1024) {
            int u = idx >> 2, g = idx & 3;
            g_bcp[idx] = bc[g * NE + u];
        }
    }
}

// ---------------- char LSTM step ----------------
// CTA: 64 tokens x 256 gate-cols (64 units). 256 threads: tx=unit(64), ty=tokgrp(4).
// Thread micro-tile: 16 tokens x 4 gate cols (= 1 unit, all gates) -> fused pointwise.
__global__ __launch_bounds__(256, 2)
void char_step_kernel(const int* __restrict__ char_idx,
                      const float* __restrict__ char_emb, int t)
{
    __shared__ float Xs[16][68];     // [k][token], padded
    __shared__ float Ws[16][260];    // [k][col],   padded
    __shared__ int   idxs[64];

    const int tid = threadIdx.x;
    const int tx = tid & 63;
    const int ty = tid >> 6;
    const int tok0 = blockIdx.x * 64;
    const int c0 = blockIdx.y * 256;

    float* hnew        = (t & 1) ? g_HcB : g_HcA;
    const float* hprev = (t & 1) ? g_HcA : g_HcB;

    float acc[16][4];
#pragma unroll
    for (int r = 0; r < 16; r++) {
        acc[r][0] = 0.f; acc[r][1] = 0.f; acc[r][2] = 0.f; acc[r][3] = 0.f;
    }

    if (tid < 64) idxs[tid] = char_idx[(tok0 + tid) * NC + t];
    __syncthreads();

    const int npass = (t == 0) ? 1 : 2;
    for (int pass = 0; pass < npass; pass++) {
        const float* W = pass ? g_WchhT : g_WcihT;
        for (int kc = 0; kc < 16; kc++) {
            const int k0 = kc * 16;
            // load Xs[k][tok] (transposed): thread loads float4 along k for one token
            {
                int tok = tid >> 2, kq = tid & 3;
                float4 v;
                if (pass == 0)
                    v = *(const float4*)&char_emb[idxs[tok] * NE + k0 + kq * 4];
                else
                    v = *(const float4*)&hprev[(tok0 + tok) * NE + k0 + kq * 4];
                Xs[kq * 4 + 0][tok] = v.x;
                Xs[kq * 4 + 1][tok] = v.y;
                Xs[kq * 4 + 2][tok] = v.z;
                Xs[kq * 4 + 3][tok] = v.w;
            }
            // load Ws[k][c]: 16x256 = 1024 float4, 4 per thread
#pragma unroll
            for (int j = 0; j < 4; j++) {
                int f = tid + j * 256;
                int kk = f >> 6, cq = f & 63;
                *(float4*)&Ws[kk][cq * 4] =
                    *(const float4*)&W[(k0 + kk) * 1024 + c0 + cq * 4];
            }
            __syncthreads();
#pragma unroll
            for (int k = 0; k < 16; k++) {
                float4 b = *(float4*)&Ws[k][tx * 4];
                float a[16];
#pragma unroll
                for (int q = 0; q < 4; q++) {
                    float4 av = *(float4*)&Xs[k][ty * 16 + q * 4];
                    a[q * 4 + 0] = av.x; a[q * 4 + 1] = av.y;
                    a[q * 4 + 2] = av.z; a[q * 4 + 3] = av.w;
                }
#pragma unroll
                for (int r = 0; r < 16; r++) {
                    acc[r][0] += a[r] * b.x;
                    acc[r][1] += a[r] * b.y;
                    acc[r][2] += a[r] * b.z;
                    acc[r][3] += a[r] * b.w;
                }
            }
            __syncthreads();
        }
    }

    // fused LSTM pointwise epilogue
    const int u = (c0 >> 2) + tx;                  // global unit 0..255
    float4 bias = *(const float4*)&g_bcp[c0 + tx * 4];
#pragma unroll
    for (int r = 0; r < 16; r++) {
        int tok = tok0 + ty * 16 + r;
        float gi = acc[r][0] + bias.x;
        float gf = acc[r][1] + bias.y;
        float gg = acc[r][2] + bias.z;
        float go = acc[r][3] + bias.w;
        float cp = (t == 0) ? 0.f : g_Cc[tok * NE + u];
        float cn = sigm_(gf) * cp + sigm_(gi) * tanh_(gg);
        float h  = sigm_(go) * tanh_(cn);
        g_Cc[tok * NE + u] = cn;
        hnew[tok * NE + u] = h;
    }
}

// ---------------- word-input GEMM: XW = [we ; char_feat] @ WwihT + bw ----------------
__global__ __launch_bounds__(256, 2)
void xw_kernel(const int* __restrict__ word_idx, const float* __restrict__ word_emb)
{
    __shared__ float Xs[16][68];
    __shared__ float Ws[16][260];
    __shared__ int   idxs[64];

    const int tid = threadIdx.x;
    const int tx = tid & 63;
    const int ty = tid >> 6;
    const int tok0 = blockIdx.x * 64;
    const int c0 = blockIdx.y * 256;

    float acc[16][4];
#pragma unroll
    for (int r = 0; r < 16; r++) {
        acc[r][0] = 0.f; acc[r][1] = 0.f; acc[r][2] = 0.f; acc[r][3] = 0.f;
    }

    if (tid < 64) idxs[tid] = word_idx[tok0 + tid];
    __syncthreads();

    for (int kc = 0; kc < 32; kc++) {
        const int k0 = kc * 16;
        {
            int tok = tid >> 2, kq = tid & 3;
            float4 v;
            if (kc < 16)
                v = *(const float4*)&word_emb[(size_t)idxs[tok] * NE + k0 + kq * 4];
            else
                v = *(const float4*)&g_HcB[(tok0 + tok) * NE + (k0 - NE) + kq * 4];
            Xs[kq * 4 + 0][tok] = v.x;
            Xs[kq * 4 + 1][tok] = v.y;
            Xs[kq * 4 + 2][tok] = v.z;
            Xs[kq * 4 + 3][tok] = v.w;
        }
#pragma unroll
        for (int j = 0; j < 4; j++) {
            int f = tid + j * 256;
            int kk = f >> 6, cq = f & 63;
            *(float4*)&Ws[kk][cq * 4] =
                *(const float4*)&g_WwihT[(k0 + kk) * 2048 + c0 + cq * 4];
        }
        __syncthreads();
#pragma unroll
        for (int k = 0; k < 16; k++) {
            float4 b = *(float4*)&Ws[k][tx * 4];
            float a[16];
#pragma unroll
            for (int q = 0; q < 4; q++) {
                float4 av = *(float4*)&Xs[k][ty * 16 + q * 4];
                a[q * 4 + 0] = av.x; a[q * 4 + 1] = av.y;
                a[q * 4 + 2] = av.z; a[q * 4 + 3] = av.w;
            }
#pragma unroll
            for (int r = 0; r < 16; r++) {
                acc[r][0] += a[r] * b.x;
                acc[r][1] += a[r] * b.y;
                acc[r][2] += a[r] * b.z;
                acc[r][3] += a[r] * b.w;
            }
        }
        __syncthreads();
    }

    float4 bias = *(const float4*)&g_bwp[c0 + tx * 4];
#pragma unroll
    for (int r = 0; r < 16; r++) {
        int tok = tok0 + ty * 16 + r;
        float4 o;
        o.x = acc[r][0] + bias.x;
        o.y = acc[r][1] + bias.y;
        o.z = acc[r][2] + bias.z;
        o.w = acc[r][3] + bias.w;
        *(float4*)&g_XW[(size_t)tok * 2048 + c0 + tx * 4] = o;
    }
}

// ---------------- word LSTM helpers: smem layout ----------------
// ws: [512][20] weight slice (16 cols padded to 20)    -> 40960 B
// hs: [32][516] h_prev, b-major, padded row            -> 66048 B
#define WORD_WS_FLOATS (512 * 20)
#define WORD_HS_STRIDE 516
#define WORD_SMEM_BYTES ((WORD_WS_FLOATS + NB * WORD_HS_STRIDE) * 4)

// Fill hs[b][k] from g_Hsave(t-1) with float4 loads/stores (32 LDG.128/thread).
__device__ __forceinline__ void word_fill_hs(float* hs, int t, int tid)
{
    if (t == 0) {
        for (int i = tid; i < NB * WORD_HS_STRIDE; i += 128) hs[i] = 0.f;
    } else {
#pragma unroll 4
        for (int i = tid; i < 4096; i += 128) {            // 4096 float4 = 32b x 128
            int bb = i >> 7, k4 = i & 127;
            float4 v = *(const float4*)&g_Hsave[(size_t)((bb << 10) + (t - 1)) * NH + k4 * 4];
            *(float4*)&hs[bb * WORD_HS_STRIDE + k4 * 4] = v;
        }
    }
}

// Inner product: 4 gate-cols (ul) over 512 k, h as float4.
__device__ __forceinline__ float4 word_dot(const float* hrow, const float* ws, int ul)
{
    float4 acc = make_float4(0.f, 0.f, 0.f, 0.f);
#pragma unroll 8
    for (int k = 0; k < 512; k += 4) {
        float4 h4 = *(const float4*)&hrow[k];
        float4 w0 = *(const float4*)&ws[(k + 0) * 20 + ul * 4];
        float4 w1 = *(const float4*)&ws[(k + 1) * 20 + ul * 4];
        float4 w2 = *(const float4*)&ws[(k + 2) * 20 + ul * 4];
        float4 w3 = *(const float4*)&ws[(k + 3) * 20 + ul * 4];
        acc.x += h4.x * w0.x; acc.y += h4.x * w0.y; acc.z += h4.x * w0.z; acc.w += h4.x * w0.w;
        acc.x += h4.y * w1.x; acc.y += h4.y * w1.y; acc.z += h4.y * w1.z; acc.w += h4.y * w1.w;
        acc.x += h4.z * w2.x; acc.y += h4.z * w2.y; acc.z += h4.z * w2.z; acc.w += h4.z * w2.w;
        acc.x += h4.w * w3.x; acc.y += h4.w * w3.y; acc.z += h4.w * w3.z; acc.w += h4.w * w3.w;
    }
    return acc;
}

// ---------------- word LSTM, cooperative (1 launch, grid.sync) ----------------
// 128 CTAs; CTA owns 16 gate-cols (4 units) x all 32 batches. c-state in register.
__global__ __launch_bounds__(128, 1)
void word_coop_kernel(int /*dummy*/)
{
    cg::grid_group grid = cg::this_grid();

    extern __shared__ float sm[];
    float* ws = sm;
    float* hs = sm + WORD_WS_FLOATS;

    const int tid = threadIdx.x;
    const int b  = tid >> 2;
    const int ul = tid & 3;
    const int c0 = blockIdx.x * 16;
    const int ug = (c0 >> 2) + ul;                 // global unit 0..511

    // load weight slice once for all 1024 steps
    for (int idx = tid; idx < 512 * 16; idx += 128) {
        int k = idx >> 4, j = idx & 15;
        ws[k * 20 + j] = g_WwhhT[k * 2048 + c0 + j];
    }

    float c = 0.f;
    for (int t = 0; t < NS; t++) {
        word_fill_hs(hs, t, tid);
        __syncthreads();

        float4 a = *(const float4*)&g_XW[(size_t)((b << 10) + t) * 2048 + c0 + ul * 4];
        float4 acc = word_dot(&hs[b * WORD_HS_STRIDE], ws, ul);

        float gi = acc.x + a.x;     // bias already folded into XW
        float gf = acc.y + a.y;
        float gg = acc.z + a.z;
        float go = acc.w + a.w;
        c = sigm_(gf) * c + sigm_(gi) * tanh_(gg);
        float h = sigm_(go) * tanh_(c);
        g_Hsave[(size_t)((b << 10) + t) * NH + ug] = h;

        grid.sync();   // grid-wide barrier with memory ordering; also fences hs reuse
    }
}

// ---------------- word LSTM fallback: one launch per step ----------------
__global__ __launch_bounds__(128, 1)
void word_step_kernel(int t)
{
    extern __shared__ float sm[];
    float* ws = sm;
    float* hs = sm + WORD_WS_FLOATS;

    const int tid = threadIdx.x;
    const int b  = tid >> 2;
    const int ul = tid & 3;
    const int c0 = blockIdx.x * 16;
    const int ug = (c0 >> 2) + ul;

    for (int idx = tid; idx < 512 * 16; idx += 128) {
        int k = idx >> 4, j = idx & 15;
        ws[k * 20 + j] = g_WwhhT[k * 2048 + c0 + j];
    }
    word_fill_hs(hs, t, tid);
    __syncthreads();

    float4 a = *(const float4*)&g_XW[(size_t)((b << 10) + t) * 2048 + c0 + ul * 4];
    float4 acc = word_dot(&hs[b * WORD_HS_STRIDE], ws, ul);

    float gi = acc.x + a.x;
    float gf = acc.y + a.y;
    float gg = acc.z + a.z;
    float go = acc.w + a.w;
    float c = (t == 0) ? 0.f : g_Cw[b * NH + ug];
    c = sigm_(gf) * c + sigm_(gi) * tanh_(gg);
    float h = sigm_(go) * tanh_(c);
    g_Cw[b * NH + ug] = c;
    g_Hsave[(size_t)((b << 10) + t) * NH + ug] = h;
}

// ---------------- logits + log_softmax ----------------
// Block: 256 thr = 4 tokens x 64 tags. Wt transposed in smem [k][64].
__global__ __launch_bounds__(256, 1)
void logits_kernel(const float* __restrict__ Wt, const float* __restrict__ bt,
                   float* __restrict__ out)
{
    extern __shared__ float sm[];
    float* Wts = sm;               // [512][65]
    float* hs  = sm + 512 * 65;    // [4][512]
    __shared__ float sl[4][64];

    const int tid = threadIdx.x;
    for (int idx = tid; idx < 512 * 64; idx += 256) {
        int tg = idx >> 9, k = idx & 511;
        Wts[k * 65 + tg] = (tg < NT) ? Wt[tg * NH + k] : 0.f;
    }
    const int tokl = tid >> 6, tag = tid & 63;
    const int wid = tid >> 5, lane = tid & 31;
    float btv = (tag < NT) ? bt[tag] : 0.f;

    for (int tb = blockIdx.x; tb < NTOK / 4; tb += gridDim.x) {
        __syncthreads();
        for (int idx = tid; idx < 2048; idx += 256) {
            int tk = idx >> 9, k = idx & 511;
            hs[tk * 512 + k] = g_Hsave[(size_t)(tb * 4 + tk) * NH + k];
        }
        __syncthreads();
        float acc = 0.f;
#pragma unroll 8
        for (int k = 0; k < 512; k++)
            acc += hs[tokl * 512 + k] * Wts[k * 65 + tag];
        sl[tokl][tag] = (tag < NT) ? (acc + btv) : -1e30f;
        __syncthreads();
        if (wid < 4) {
            float l0 = sl[wid][lane], l1 = sl[wid][lane + 32];
            float m = fmaxf(l0, l1);
#pragma unroll
            for (int o = 16; o; o >>= 1) m = fmaxf(m, __shfl_xor_sync(0xffffffffu, m, o));
            float s = __expf(l0 - m) + __expf(l1 - m);
#pragma unroll
            for (int o = 16; o; o >>= 1) s += __shfl_xor_sync(0xffffffffu, s, o);
            float lse = m + __logf(s);
            int n = tb * 4 + wid;
            for (int j = lane; j < NT; j += 32)
                out[(size_t)n * NT + j] = sl[wid][j] - lse;
        }
    }
}

// ---------------- launch ----------------
extern "C" void kernel_launch(void* const* d_in, const int* in_sizes, int n_in,
                              void* d_out, int out_size)
{
    const int*   char_idx = (const int*)d_in[0];
    const int*   word_idx = (const int*)d_in[1];
    const float* char_emb = (const float*)d_in[2];
    const float* word_emb = (const float*)d_in[3];
    const float* Wc_ih    = (const float*)d_in[4];
    const float* Wc_hh    = (const float*)d_in[5];
    const float* bc       = (const float*)d_in[6];
    const float* Ww_ih    = (const float*)d_in[7];
    const float* Ww_hh    = (const float*)d_in[8];
    const float* bw       = (const float*)d_in[9];
    const float* Wt       = (const float*)d_in[10];
    const float* bt       = (const float*)d_in[11];
    float* out = (float*)d_out;

    const int word_smem   = WORD_SMEM_BYTES;             // 107008 B
    const int logits_smem = (512 * 65 + 4 * 512) * 4;    // 141312 B
    cudaFuncSetAttribute(word_coop_kernel,
                         cudaFuncAttributeMaxDynamicSharedMemorySize, word_smem);
    cudaFuncSetAttribute(word_step_kernel,
                         cudaFuncAttributeMaxDynamicSharedMemorySize, word_smem);
    cudaFuncSetAttribute(logits_kernel,
                         cudaFuncAttributeMaxDynamicSharedMemorySize, logits_smem);

    // Deterministic host-side decision: cooperative path only if the device
    // guarantees 128 co-resident CTAs (pure queries, capture-legal).
    int dev = 0;
    cudaGetDevice(&dev);
    int numSM = 0, coopAttr = 0, perSM = 0;
    cudaDeviceGetAttribute(&numSM, cudaDevAttrMultiProcessorCount, dev);
    cudaDeviceGetAttribute(&coopAttr, cudaDevAttrCooperativeLaunch, dev);
    cudaOccupancyMaxActiveBlocksPerMultiprocessor(&perSM, word_coop_kernel, 128, word_smem);
    const bool coop_ok = (coopAttr != 0) && (perSM >= 1) && (numSM >= 128);

    prep_all_kernel<<<4096, 256>>>(Wc_ih, Wc_hh, bc, Ww_ih, Ww_hh, bw);

    for (int t = 0; t < NC; t++)
        char_step_kernel<<<dim3(NTOK / 64, 4), 256>>>(char_idx, char_emb, t);

    xw_kernel<<<dim3(NTOK / 64, 8), 256>>>(word_idx, word_emb);

    if (coop_ok) {
        int dummy = 0;
        void* kargs[] = { &dummy };
        cudaLaunchCooperativeKernel((void*)word_coop_kernel,
                                    dim3(128), dim3(128),
                                    kargs, (size_t)word_smem, (cudaStream_t)0);
    } else {
        for (int t = 0; t < NS; t++)
            word_step_kernel<<<128, 128, word_smem>>>(t);
    }

    logits_kernel<<<148, 256, logits_smem>>>(Wt, bt, out);
}